// round 8
// baseline (speedup 1.0000x reference)
#include <cuda_runtime.h>
#include <cstdint>

typedef unsigned long long u64;

#define NQ 16384
#define NB 128
#define NF 64
#define HD 128
#define EPSF 1e-8f

#define THREADS 1024
#define WARPS_PER_CTA 32
#define PAIRS_PER_CTA 16
#define MAXQ 4      // q's per batch = 2 jp q-pairs
#define JPMAX 2

// Packed probe tables (prep output). Pair p couples b=p and b=p+64.
// g_probeA[f][p] = {P_real[p], P_real[p+64], P_imag[p], P_imag[p+64]}
// g_probeB[f][p] = {w[p],      w[p+64],      mw[p],     mw[p+64]}
__device__ float g_probeA[NF * 64 * 4];
__device__ float g_probeB[NF * 64 * 4];

// ---------- f32x2 helpers ----------
__device__ __forceinline__ u64 f2pk(float lo, float hi) {
    u64 r; asm("mov.b64 %0, {%1,%2};" : "=l"(r) : "f"(lo), "f"(hi)); return r;
}
__device__ __forceinline__ void f2upk(float& lo, float& hi, u64 v) {
    asm("mov.b64 {%0,%1}, %2;" : "=f"(lo), "=f"(hi) : "l"(v));
}
__device__ __forceinline__ u64 f2add(u64 a, u64 b) {
    u64 d; asm("add.rn.f32x2 %0, %1, %2;" : "=l"(d) : "l"(a), "l"(b)); return d;
}
__device__ __forceinline__ u64 f2fma(u64 a, u64 b, u64 c) {
    u64 d; asm("fma.rn.f32x2 %0, %1, %2, %3;" : "=l"(d) : "l"(a), "l"(b), "l"(c)); return d;
}
__device__ __forceinline__ float sqrt_apx(float x) {
    float r; asm("sqrt.approx.f32 %0, %1;" : "=f"(r) : "f"(x)); return r;
}
__device__ __forceinline__ float rcp_apx(float x) {
    float r; asm("rcp.approx.f32 %0, %1;" : "=f"(r) : "f"(x)); return r;
}
__device__ __forceinline__ uint32_t su32(const void* p) {
    uint32_t a;
    asm("{ .reg .u64 t; cvta.to.shared.u64 t, %1; cvt.u32.u64 %0, t; }"
        : "=r"(a) : "l"(p));
    return a;
}

// ---------- prep: one block per probe b, one thread per f ----------
__global__ __launch_bounds__(64)
void prep_kernel(const float* __restrict__ probes,
                 const float* __restrict__ angles,
                 const float* __restrict__ qw,
                 const float* __restrict__ qmw) {
    __shared__ float red[2];
    const int b = blockIdx.x;   // 0..127
    const int f = threadIdx.x;  // 0..63
    const int warp = f >> 5;
    const int lane = f & 31;

    float x0 = probes[b * HD + f];
    float x1 = probes[b * HD + NF + f];
    float ss = fmaf(x0, x0, x1 * x1);
#pragma unroll
    for (int o = 16; o; o >>= 1) ss += __shfl_xor_sync(0xffffffffu, ss, o);
    if (lane == 0) red[warp] = ss;
    __syncthreads();
    float inv = 1.0f / (sqrtf(red[0] + red[1]) + EPSF);

    float pr = x0 * inv;
    float pi = x1 * inv;
    float c, s;
    sincosf(angles[f], &s, &c);
    float Pr = pr * c - pi * s;
    float Pi = pr * s + pi * c;
    float xw = qw[b * NF + f];
    float sp = (xw > 20.0f) ? xw : log1pf(expf(xw));
    float w = -sp;
    float mw = qmw[b * NF + f];

    int p = b & 63;
    int hi = b >> 6;
    int base = (f * 64 + p) * 4;
    g_probeA[base + 0 + hi] = Pr;
    g_probeA[base + 2 + hi] = Pi;
    g_probeB[base + 0 + hi] = w;
    g_probeB[base + 2 + hi] = mw;
}

// ---------- SMEM layout (float offsets) ----------
#define OFF_SA  0        // probeA: 16384 floats (64KB)
#define OFF_SB  16384    // probeB: 16384 floats (64KB)
#define OFF_QTA 32768    // q-pair table A: 16 pairs * 2jp * 64f * 4 = 8192 floats (32KB)
                         //   entry: {-qr_j, -qr_j', -qi_j, -qi_j'}
#define OFF_QTM 40960    // q-pair table M: 16 pairs * 2jp * 64f * 2 = 4096 floats (16KB)
                         //   entry: {qm_j, qm_j'}
#define OFF_QN  45056    // per-warp qn scratch: 32*128 = 4096 floats (16KB)
#define SMEM_FLOATS 49152 // 192 KB

// Batch of JP q-pairs (up to 2*JP q's; last may be duplicated). Lane handles
// b-pair (p, p+64); f32x2 halves are the two q's of each jp.
template<int JP>
__device__ __forceinline__ void run_batch(uint32_t aA0, uint32_t aB0,
                                          uint32_t aQTA, uint32_t aQTM,
                                          u64 biasA, u64 biasB, u64 EPS2,
                                          float* __restrict__ out,
                                          int q0, int jn, int p) {
    u64 accA[JP], accB[JP];
#pragma unroll
    for (int jp = 0; jp < JP; jp++) { accA[jp] = biasA; accB[jp] = biasB; }

#pragma unroll 2
    for (int f = 0; f < NF; f++) {
        const uint32_t fo = (uint32_t)f * 1024u;
        float PrA, PrB, PiA, PiB, wA, wB, mwA, mwB;
        asm("ld.shared.v4.f32 {%0,%1,%2,%3}, [%4];"
            : "=f"(PrA), "=f"(PrB), "=f"(PiA), "=f"(PiB) : "r"(aA0 + fo));
        asm("ld.shared.v4.f32 {%0,%1,%2,%3}, [%4];"
            : "=f"(wA), "=f"(wB), "=f"(mwA), "=f"(mwB) : "r"(aB0 + fo));
        const u64 PrA2 = f2pk(PrA, PrA), PrB2 = f2pk(PrB, PrB);
        const u64 PiA2 = f2pk(PiA, PiA), PiB2 = f2pk(PiB, PiB);
        const u64 wA2  = f2pk(wA, wA),   wB2  = f2pk(wB, wB);
        const u64 mwA2 = f2pk(mwA, mwA), mwB2 = f2pk(mwB, mwB);

#pragma unroll
        for (int jp = 0; jp < JP; jp++) {
            // lane-invariant addresses -> broadcast LDS (1 wavefront)
            u64 nqr, nqi, qm2;
            asm("ld.shared.v2.b64 {%0,%1}, [%2];"
                : "=l"(nqr), "=l"(nqi)
                : "r"(aQTA + ((uint32_t)jp * 64u + (uint32_t)f) * 16u));
            asm("ld.shared.b64 %0, [%1];"
                : "=l"(qm2)
                : "r"(aQTM + ((uint32_t)jp * 64u + (uint32_t)f) * 8u));

            // b = p
            {
                u64 er = f2add(PrA2, nqr);
                u64 ei = f2add(PiA2, nqi);
                u64 d2 = f2fma(er, er, f2fma(ei, ei, EPS2));
                float lo, hi; f2upk(lo, hi, d2);
                u64 dist = f2pk(sqrt_apx(lo), sqrt_apx(hi));
                accA[jp] = f2fma(dist, wA2, accA[jp]);
                accA[jp] = f2fma(qm2, mwA2, accA[jp]);
            }
            // b = p + 64
            {
                u64 er = f2add(PrB2, nqr);
                u64 ei = f2add(PiB2, nqi);
                u64 d2 = f2fma(er, er, f2fma(ei, ei, EPS2));
                float lo, hi; f2upk(lo, hi, d2);
                u64 dist = f2pk(sqrt_apx(lo), sqrt_apx(hi));
                accB[jp] = f2fma(dist, wB2, accB[jp]);
                accB[jp] = f2fma(qm2, mwB2, accB[jp]);
            }
        }
    }

#pragma unroll
    for (int jp = 0; jp < JP; jp++) {
        const int j0 = 2 * jp, j1 = 2 * jp + 1;
        float a0, a1, b0, b1;
        f2upk(a0, a1, accA[jp]);
        f2upk(b0, b1, accB[jp]);
        float* r0 = out + (size_t)(q0 + j0) * NB;
        r0[p] = a0; r0[p + 64] = b0;
        if (j1 < jn) {
            float* r1 = out + (size_t)(q0 + j1) * NB;
            r1[p] = a1; r1[p + 64] = b1;
        }
    }
}

__global__ __launch_bounds__(THREADS, 1)
void main_kernel(const float* __restrict__ Q,
                 const float* __restrict__ bias,
                 float* __restrict__ out) {
    extern __shared__ float sm[];
    const int tid  = threadIdx.x;
    const int warp = tid >> 5;
    const int lane = tid & 31;
    const int pid  = warp >> 1;     // pair id 0..15
    const int h    = warp & 1;      // warp half within pair
    const int p    = lane + 32 * h; // b-pair index 0..63

    // Stage probe tables into SMEM
    {
        const float4* gA = (const float4*)g_probeA;
        const float4* gB = (const float4*)g_probeB;
        float4* sA4 = (float4*)(sm + OFF_SA);
        float4* sB4 = (float4*)(sm + OFF_SB);
        for (int i = tid; i < NF * 64; i += THREADS) {
            sA4[i] = gA[i];
            sB4[i] = gB[i];
        }
    }

    const u64 biasA = f2pk(bias[p], bias[p]);           // halves are q's: duplicate
    const u64 biasB = f2pk(bias[p + 64], bias[p + 64]);
    const u64 EPS2  = f2pk(EPSF, EPSF);

    __syncthreads();

    const uint32_t sbase = su32(sm);
    const uint32_t aA0  = sbase + (uint32_t)p * 16u;
    const uint32_t aB0  = sbase + (uint32_t)OFF_SB * 4u + (uint32_t)p * 16u;
    const uint32_t aQTA = sbase + ((uint32_t)OFF_QTA + (uint32_t)pid * (JPMAX * 64 * 4)) * 4u;
    const uint32_t aQTM = sbase + ((uint32_t)OFF_QTM + (uint32_t)pid * (JPMAX * 64 * 2)) * 4u;
    float* qn  = sm + OFF_QN + warp * 128;
    float* qta = sm + OFF_QTA + pid * (JPMAX * 64 * 4);
    float* qtm = sm + OFF_QTM + pid * (JPMAX * 64 * 2);

    // ---- contiguous q-range per warp-pair (balanced to +/-1 q) ----
    const int npairs = gridDim.x * PAIRS_PER_CTA;
    const int gp = blockIdx.x * PAIRS_PER_CTA + pid;
    const int per = NQ / npairs;
    const int rem = NQ % npairs;
    int cnt, q0;
    if (gp < rem) { cnt = per + 1; q0 = gp * (per + 1); }
    else          { cnt = per;     q0 = rem * (per + 1) + (gp - rem) * per; }

    while (cnt > 0) {
        const int jn = (cnt > MAXQ) ? MAXQ : cnt;
        const bool odd = (jn & 1) != 0;

        // ---- batch prep: warps split q's by parity ----
        for (int j = h; j < jn; j += 2) {
            const float4* Qv = (const float4*)(Q + (size_t)(q0 + j) * HD);
            float4 v = Qv[lane];
            float ss = fmaf(v.x, v.x, fmaf(v.y, v.y, fmaf(v.z, v.z, v.w * v.w)));
#pragma unroll
            for (int o = 16; o; o >>= 1) ss += __shfl_xor_sync(0xffffffffu, ss, o);
            float inv = rcp_apx(sqrt_apx(ss) + EPSF);
            ((float4*)qn)[lane] = make_float4(v.x * inv, v.y * inv, v.z * inv, v.w * inv);
            __syncwarp();
            const int jp = j >> 1, half = j & 1;
            const bool dup = odd && (j == jn - 1);
#pragma unroll
            for (int k = 0; k < 2; k++) {
                int f = lane + k * 32;
                float qr = qn[f];
                float qi = qn[f + 64];
                float qm = sqrt_apx(fmaf(qr, qr, fmaf(qi, qi, EPSF)));
                float* qa  = qta + (jp * 64 + f) * 4;
                float* qm_ = qtm + (jp * 64 + f) * 2;
                qa[half]     = -qr;
                qa[2 + half] = -qi;
                qm_[half]    = qm;
                if (dup) { qa[1] = -qr; qa[3] = -qi; qm_[1] = qm; }
            }
            __syncwarp();
        }
        // pair-scoped named barrier (id = pid, 0..15; bar0 free after init sync)
        asm volatile("bar.sync %0, %1;" :: "r"(pid), "r"(64) : "memory");

        if (jn > 2) run_batch<2>(aA0, aB0, aQTA, aQTM, biasA, biasB, EPS2, out, q0, jn, p);
        else        run_batch<1>(aA0, aB0, aQTA, aQTM, biasA, biasB, EPS2, out, q0, jn, p);

        // protect q-tables against next batch's overwrite
        asm volatile("bar.sync %0, %1;" :: "r"(pid), "r"(64) : "memory");

        q0 += jn;
        cnt -= jn;
    }
}

extern "C" void kernel_launch(void* const* d_in, const int* in_sizes, int n_in,
                              void* d_out, int out_size) {
    const float* Q      = (const float*)d_in[0];
    const float* angles = (const float*)d_in[1];
    const float* probes = (const float*)d_in[2];
    const float* qw     = (const float*)d_in[3];
    const float* qmw    = (const float*)d_in[4];
    const float* qbias  = (const float*)d_in[5];
    float* out = (float*)d_out;

    static_assert(OFF_SB  == OFF_SA + NF * 64 * 4, "probeA region");
    static_assert(OFF_QTA == OFF_SB + NF * 64 * 4, "probeB region");
    static_assert(OFF_QTM == OFF_QTA + PAIRS_PER_CTA * JPMAX * 64 * 4, "qtA region");
    static_assert(OFF_QN  == OFF_QTM + PAIRS_PER_CTA * JPMAX * 64 * 2, "qtM region");
    static_assert(SMEM_FLOATS == OFF_QN + WARPS_PER_CTA * 128, "qn region");
    static_assert(SMEM_FLOATS * sizeof(float) <= 196608, "smem cap for 1024thr");

    cudaFuncSetAttribute(main_kernel,
                         cudaFuncAttributeMaxDynamicSharedMemorySize,
                         SMEM_FLOATS * (int)sizeof(float));

    int sms = 148;
    cudaDeviceGetAttribute(&sms, cudaDevAttrMultiProcessorCount, 0);

    prep_kernel<<<NB, 64>>>(probes, angles, qw, qmw);
    main_kernel<<<sms, THREADS, SMEM_FLOATS * sizeof(float)>>>(Q, qbias, out);
}